// round 16
// baseline (speedup 1.0000x reference)
#include <cuda_runtime.h>
#include <cstdint>
#include <math.h>

// ---------------- problem constants ----------------
#define BQ     32
#define LQ     128
#define HQ     200
#define MROWS  4096          // L*B rows, row m = t*32 + b
#define IND    550
#define KP0    560           // padded K for layer0 A
#define K1     400
#define NG     800           // 4*H gates
#define XGP    832           // padded gate stride (13 * 64)
#define NPAIR  8001
#define SPAN_BSTRIDE (NPAIR*400)          // 3,200,400
#define SPAN_TOTAL   (BQ*NPAIR*400)       // 102,412,800

// recurrence sharding (v9 — unchanged from R15 win)
#define RNK    8             // CTAs per cluster (owns 25 h-cols each)
#define RBG    4             // batches per cluster
#define KSL    28            // k elements per k-slice (8*28 = 224 >= 200)
#define HSP    228           // padded hs row stride (floats)
#define NBUF   4             // quad-buffered h exchange
#define SENTINEL 0x7F7FFFFFu // FLT_MAX bits; h = sig*tanh in (-1,1), never this

// ---------------- device scratch (no runtime allocation) ----------------
__device__ float g_x0[MROWS * KP0];          // embedded input, zero-padded K
__device__ float g_xg[2 * MROWS * XGP];      // gate pre-activations (reused both layers)
__device__ float g_h0[MROWS * 400];          // layer0 output  [t*32+b][dir*200+c]
__device__ float g_h1[MROWS * 400];          // layer1 output

// ---------------- helpers ----------------
__device__ __forceinline__ float sigf(float x) {
    return __fdividef(1.0f, 1.0f + __expf(-x));
}
__device__ __forceinline__ float tanh_fast(float x) {
    return 2.0f * __fdividef(1.0f, 1.0f + __expf(-2.0f * x)) - 1.0f;
}

__device__ __forceinline__ uint32_t f2tf32(float x) {
    uint32_t r;
    asm("cvt.rna.tf32.f32 %0, %1;" : "=r"(r) : "f"(x));
    return r;
}

__device__ __forceinline__ unsigned long long packf2(float x, float y) {
    unsigned long long r;
    asm("mov.b64 %0, {%1, %2};" : "=l"(r) : "f"(x), "f"(y));
    return r;
}
__device__ __forceinline__ void unpackf2(unsigned long long v, float& lo, float& hi) {
    asm("mov.b64 {%0, %1}, %2;" : "=f"(lo), "=f"(hi) : "l"(v));
}
__device__ __forceinline__ unsigned long long fma2(unsigned long long a,
                                                   unsigned long long b,
                                                   unsigned long long c) {
    unsigned long long d;
    asm("fma.rn.f32x2 %0, %1, %2, %3;" : "=l"(d) : "l"(a), "l"(b), "l"(c));
    return d;
}
__device__ __forceinline__ uint32_t smem_u32(const void* p) {
    uint32_t a;
    asm("{ .reg .u64 t; cvta.to.shared.u64 t, %1; cvt.u32.u64 %0, t; }"
        : "=r"(a) : "l"(p));
    return a;
}
__device__ __forceinline__ uint32_t mapa_u32(uint32_t addr, uint32_t rank) {
    uint32_t r;
    asm("mapa.shared::cluster.u32 %0, %1, %2;" : "=r"(r) : "r"(addr), "r"(rank));
    return r;
}

// =====================================================================
// Kernel 1: embedding gather
// =====================================================================
__global__ void __launch_bounds__(256) emb_kernel(
    const int* __restrict__ lang, const int* __restrict__ word,
    const int* __restrict__ pos,  const int* __restrict__ dep,
    const int* __restrict__ ent,  const int* __restrict__ iob,
    const float* __restrict__ El, const float* __restrict__ Ew,
    const float* __restrict__ Ep, const float* __restrict__ Ed,
    const float* __restrict__ Ee, const float* __restrict__ Ei)
{
    int m = blockIdx.x;                 // t*32 + b
    int t = m >> 5, b = m & 31;
    int tid = threadIdx.x;

    int li = lang[b * LQ + t];
    int wi = word[b * LQ + t];
    int pi = pos[b * LQ + t];
    int di = dep[b * LQ + t];
    int ei = ent[b * LQ + t];
    int ii = iob[b * LQ + t];

    float* dst = g_x0 + (size_t)m * KP0;
    for (int c = tid; c < KP0; c += 256) {
        float v;
        if      (c < 50)  v = El[li * 50  + c];
        else if (c < 350) v = Ew[wi * 300 + (c - 50)];
        else if (c < 400) v = Ep[pi * 50  + (c - 350)];
        else if (c < 450) v = Ed[di * 50  + (c - 400)];
        else if (c < 500) v = Ee[ei * 50  + (c - 450)];
        else if (c < 550) v = Ei[ii * 50  + (c - 500)];
        else              v = 0.0f;     // K padding for the tf32 GEMM
        dst[c] = v;
    }
}

// =====================================================================
// Kernel 2: xg GEMM (v2 — VECTORIZED FILL PATH).
// Same 128x64 CTA tile / 32x32 warp tile / mma loop / smem layout as v1.
// Changes: A tile filled with LDG.128 -> cvt -> STS.128 (was 4x STS.32);
// B tile filled with 2x guarded LDG.64 (float2; K=550 rows are 8B- but
// not 16B-aligned) -> cvt -> one STS.128 (was 4x LDG.32 + 4x STS.32).
// Cuts L1 wavefronts on the fill path ~3x (profile: L1=64%, tensor=23%).
// =====================================================================
template<int LAYER>
__global__ void __launch_bounds__(256) xg_gemm(
    const float* __restrict__ W, const float* __restrict__ bi,
    const float* __restrict__ bh)
{
    constexpr int K   = (LAYER == 0) ? IND : K1;
    constexpr int KPA = (LAYER == 0) ? KP0 : K1;
    const float* A = (LAYER == 0) ? g_x0 : g_h0;

    __shared__ uint32_t As[128 * 20];   // [m][k] stride 20 (80B rows, 16B-aligned)
    __shared__ uint32_t Bs[64 * 20];    // [n][k] stride 20

    int mt0 = blockIdx.x * 128;
    int nt0 = blockIdx.y * 64;
    int dir = blockIdx.z;
    const float* Wd  = W  + (size_t)dir * NG * K;
    const float* bid = bi + dir * NG;
    const float* bhd = bh + dir * NG;
    float* Cd = g_xg + (size_t)dir * MROWS * XGP;

    int tid  = threadIdx.x;
    int w    = tid >> 5, lane = tid & 31;
    int wm   = w & 3,  wn = w >> 2;          // 4 x 2 warp grid
    int gr   = lane >> 2, lc = lane & 3;

    // B fill indexing: thread -> (row n = tid>>2, quarter q = tid&3)
    int bn = tid >> 2;                  // 0..63
    int bq = (tid & 3) * 4;             // k offset 0/4/8/12

    float acc[2][4][4];
#pragma unroll
    for (int a = 0; a < 2; a++)
#pragma unroll
        for (int b2 = 0; b2 < 4; b2++)
#pragma unroll
            for (int c = 0; c < 4; c++) acc[a][b2][c] = 0.0f;

    const int KIT = KPA / 16;
    for (int kt = 0; kt < KIT; kt++) {
        int kbase = kt * 16;
        // ---- A: 128x16, 2 x (LDG.128 -> cvt -> STS.128) per thread ----
#pragma unroll
        for (int r = 0; r < 2; r++) {
            int q   = tid + r * 256;
            int row = q >> 2, c4 = (q & 3) * 4;
            float4 v = *(const float4*)(A + (size_t)(mt0 + row) * KPA + kbase + c4);
            uint4 u;
            u.x = f2tf32(v.x); u.y = f2tf32(v.y);
            u.z = f2tf32(v.z); u.w = f2tf32(v.w);
            *(uint4*)(As + row * 20 + c4) = u;
        }
        // ---- B: 64x16, 2 guarded LDG.64 -> cvt -> one STS.128 ----
        {
            int ng = nt0 + bn;
            int gk = kbase + bq;
            float2 v0 = make_float2(0.0f, 0.0f);
            float2 v1 = make_float2(0.0f, 0.0f);
            if (ng < NG) {
                const float* src = Wd + (size_t)ng * K + gk;
                if (gk + 1 < K)     v0 = *(const float2*)(src);
                else if (gk < K)    v0.x = src[0];
                if (gk + 3 < K)     v1 = *(const float2*)(src + 2);
                else if (gk + 2 < K) v1.x = src[2];
            }
            uint4 u;
            u.x = f2tf32(v0.x); u.y = f2tf32(v0.y);
            u.z = f2tf32(v1.x); u.w = f2tf32(v1.y);
            *(uint4*)(Bs + bn * 20 + bq) = u;
        }
        __syncthreads();

#pragma unroll
        for (int kk = 0; kk < 16; kk += 8) {
            uint32_t af[2][4], bf[4][2];
#pragma unroll
            for (int mt = 0; mt < 2; mt++) {
                int rb = wm * 32 + mt * 16 + gr;
                af[mt][0] = As[rb * 20 + kk + lc];
                af[mt][1] = As[(rb + 8) * 20 + kk + lc];
                af[mt][2] = As[rb * 20 + kk + lc + 4];
                af[mt][3] = As[(rb + 8) * 20 + kk + lc + 4];
            }
#pragma unroll
            for (int nt = 0; nt < 4; nt++) {
                int nb = wn * 32 + nt * 8 + gr;
                bf[nt][0] = Bs[nb * 20 + kk + lc];
                bf[nt][1] = Bs[nb * 20 + kk + lc + 4];
            }
#pragma unroll
            for (int mt = 0; mt < 2; mt++)
#pragma unroll
                for (int nt = 0; nt < 4; nt++) {
                    asm volatile(
                        "mma.sync.aligned.m16n8k8.row.col.f32.tf32.tf32.f32 "
                        "{%0,%1,%2,%3}, {%4,%5,%6,%7}, {%8,%9}, {%0,%1,%2,%3};"
                        : "+f"(acc[mt][nt][0]), "+f"(acc[mt][nt][1]),
                          "+f"(acc[mt][nt][2]), "+f"(acc[mt][nt][3])
                        : "r"(af[mt][0]), "r"(af[mt][1]), "r"(af[mt][2]), "r"(af[mt][3]),
                          "r"(bf[nt][0]), "r"(bf[nt][1]));
                }
        }
        __syncthreads();
    }

    // ---- epilogue: add (bi+bh), write padded xg ----
#pragma unroll
    for (int mt = 0; mt < 2; mt++) {
        int row0 = mt0 + wm * 32 + mt * 16 + gr;
#pragma unroll
        for (int nt = 0; nt < 4; nt++) {
            int col = nt0 + wn * 32 + nt * 8 + 2 * lc;
            if (col < NG) {
                float bs0 = bid[col] + bhd[col];
                float bs1 = bid[col + 1] + bhd[col + 1];
                Cd[(size_t)row0 * XGP + col]           = acc[mt][nt][0] + bs0;
                Cd[(size_t)row0 * XGP + col + 1]       = acc[mt][nt][1] + bs1;
                Cd[(size_t)(row0 + 8) * XGP + col]     = acc[mt][nt][2] + bs0;
                Cd[(size_t)(row0 + 8) * XGP + col + 1] = acc[mt][nt][3] + bs1;
            }
        }
    }
}

// =====================================================================
// Kernel 3: cluster BiLSTM recurrence (v9 — SENTINEL + QUAD BUFFER).
// UNCHANGED from R15 (347us/layer win config).
// =====================================================================
template<int LAYER>
__global__ void __launch_bounds__(256, 1) __cluster_dims__(RNK, 1, 1)
lstm_rec(const float* __restrict__ Whh)
{
    float* hout = (LAYER == 0) ? g_h0 : g_h1;

    __shared__ float hs[NBUF][RBG][HSP];        // quad-buffered h_prev

    int blk  = blockIdx.x;
    int rank = blk & 7;
    int bg   = (blk >> 3) & 7;          // batch group (4 batches)
    int dir  = blk >> 6;
    const bool fwd = (dir == 0);

    int tid = threadIdx.x;
    int j   = tid >> 3;                 // 0..31 (valid 0..24)
    int ks  = tid & 7;                  // k-slice
    bool jv = (j < 25);
    int col = rank * 25 + j;            // global h column (when jv)
    bool owner = jv && (ks < RBG);
    int bglob  = bg * RBG + ks;         // owner's global batch

    const float* xgd = g_xg + (size_t)dir * MROWS * XGP;
    const float* Wd  = Whh + (size_t)dir * NG * HQ;

    // ---- Whh slice into registers ----
    unsigned long long w2[4][KSL / 2];
#pragma unroll
    for (int g = 0; g < 4; g++)
#pragma unroll
        for (int kk = 0; kk < KSL / 2; kk++) {
            int k = ks * KSL + kk * 2;
            float2 v = make_float2(0.0f, 0.0f);
            if (jv && k < HQ)
                v = *(const float2*)(Wd + (size_t)(g * 200 + col) * HQ + k);
            w2[g][kk] = packf2(v.x, v.y);
        }

    // ---- spin/prime word assignment: words w = b*200+c, 800 total ----
    int nw = (tid < 800 - 3 * 256) ? 4 : 3;     // threads 0..31 get 4 words
    uint32_t woff[4];
#pragma unroll
    for (int i = 0; i < 4; i++) {
        int w = tid + i * 256;
        if (w < 800) {
            int b = w / 200, c = w - b * 200;
            woff[i] = (uint32_t)((b * HSP + c) * 4);
        } else woff[i] = 0;
    }
    uint32_t hbase0 = smem_u32(&hs[0][0][0]);
    const uint32_t BUFB = (uint32_t)(RBG * HSP * 4);    // bytes per buffer

    // ---- init: buf0 = zeros (h(-1)); bufs 1..3 data cols sentinel ----
    for (int i = tid; i < NBUF * RBG * HSP; i += 256) {
        int buf = i / (RBG * HSP);
        int r   = i - buf * (RBG * HSP);
        int c   = r % HSP;
        ((float*)hs)[i] = (buf != 0 && c < 200) ? __uint_as_float(SENTINEL) : 0.0f;
    }
    float cst = 0.0f;
    __syncthreads();
    asm volatile("barrier.cluster.arrive.aligned;" ::: "memory");
    asm volatile("barrier.cluster.wait.aligned;"   ::: "memory");

    // DSMEM publish addresses
    uint32_t rbase[RNK];
#pragma unroll
    for (int r = 0; r < RNK; r++) rbase[r] = mapa_u32(hbase0, (uint32_t)r);

    // prefetch xg for step 0
    int t0 = fwd ? 0 : (LQ - 1);
    float xv[4];
#pragma unroll
    for (int g = 0; g < 4; g++)
        xv[g] = owner ? xgd[(size_t)(t0 * 32 + bglob) * XGP + g * 200 + col] : 0.0f;

    for (int s = 0; s < LQ; s++) {
        int t   = fwd ? s : (LQ - 1 - s);
        int cur = s & 3, nxt = (s + 1) & 3, prm = (s + 2) & 3;
        bool last = (s + 1 >= LQ);
        uint32_t curb = hbase0 + (uint32_t)cur * BUFB;
        uint32_t prmb = hbase0 + (uint32_t)prm * BUFB;

        // ---- prime buf[(s+2)%4] (off the critical path) ----
        if (s + 2 < LQ) {
            for (int i = 0; i < nw; i++) {
                asm volatile("st.shared.b32 [%0], %1;"
                             :: "r"(prmb + woff[i]), "r"(SENTINEL) : "memory");
            }
        }

        // ---- spin: wait for all 800 step-(s-1) words (skip at s=0) ----
        if (s > 0) {
            bool ok;
            do {
                ok = true;
                for (int i = 0; i < nw; i++) {
                    uint32_t v;
                    asm volatile("ld.volatile.shared.b32 %0, [%1];"
                                 : "=r"(v) : "r"(curb + woff[i]));
                    ok &= (v != SENTINEL);
                }
            } while (!ok);
        }
        __syncthreads();    // barA: words confirmed + prime ordered before publish

        // ---- partial dots: sb[b][g] = slice-ks dot for batch b, gate g ----
        float sb[RBG][4];
#pragma unroll
        for (int b = 0; b < RBG; b++) {
            const float4* hp = (const float4*)(&hs[cur][b][ks * KSL]);
            unsigned long long a0 = 0ull, a1 = 0ull, a2 = 0ull, a3 = 0ull;
#pragma unroll
            for (int q = 0; q < KSL / 4; q++) {
                float4 hv = hp[q];
                unsigned long long hlo = packf2(hv.x, hv.y);
                unsigned long long hhi = packf2(hv.z, hv.w);
                a0 = fma2(w2[0][2 * q], hlo, a0); a0 = fma2(w2[0][2 * q + 1], hhi, a0);
                a1 = fma2(w2[1][2 * q], hlo, a1); a1 = fma2(w2[1][2 * q + 1], hhi, a1);
                a2 = fma2(w2[2][2 * q], hlo, a2); a2 = fma2(w2[2][2 * q + 1], hhi, a2);
                a3 = fma2(w2[3][2 * q], hlo, a3); a3 = fma2(w2[3][2 * q + 1], hhi, a3);
            }
            float lo, hi;
            unpackf2(a0, lo, hi); sb[b][0] = lo + hi;
            unpackf2(a1, lo, hi); sb[b][1] = lo + hi;
            unpackf2(a2, lo, hi); sb[b][2] = lo + hi;
            unpackf2(a3, lo, hi); sb[b][3] = lo + hi;
        }

        // ---- transpose-reduce over ks (16 shfls) ----
        bool pl = (ks & 1) == 0;
        float k0[4], k2[4];
#pragma unroll
        for (int g = 0; g < 4; g++) {
            float s01 = pl ? sb[1][g] : sb[0][g];
            float s23 = pl ? sb[3][g] : sb[2][g];
            float r01 = __shfl_xor_sync(0xffffffffu, s01, 1);
            float r23 = __shfl_xor_sync(0xffffffffu, s23, 1);
            k0[g] = (pl ? sb[0][g] : sb[1][g]) + r01;
            k2[g] = (pl ? sb[2][g] : sb[3][g]) + r23;
        }
        bool p2 = ((ks >> 1) & 1) == 0;
        float kq[4];
#pragma unroll
        for (int g = 0; g < 4; g++) {
            float sx = p2 ? k2[g] : k0[g];
            float r  = __shfl_xor_sync(0xffffffffu, sx, 2);
            kq[g] = (p2 ? k0[g] : k2[g]) + r;
        }
        bool p4 = (ks >> 2) == 0;
        float sA = p4 ? kq[2] : kq[0];
        float sB = p4 ? kq[3] : kq[1];
        float rA = __shfl_xor_sync(0xffffffffu, sA, 4);
        float rB = __shfl_xor_sync(0xffffffffu, sB, 4);
        float f0 = (p4 ? kq[0] : kq[2]) + rA;
        float f1 = (p4 ? kq[1] : kq[3]) + rB;
        float g2 = __shfl_xor_sync(0xffffffffu, f0, 4);
        float g3 = __shfl_xor_sync(0xffffffffu, f1, 4);

        // ---- activations + publish (owners: 25 cols x 4 batches) ----
        float hvout = 0.0f;
        if (owner) {
            float gi = f0 + xv[0];
            float gf = f1 + xv[1];
            float gg = g2 + xv[2];
            float go = g3 + xv[3];
            float cn = sigf(gf) * cst + sigf(gi) * tanh_fast(gg);
            cst = cn;
            hvout = sigf(go) * tanh_fast(cn);
            if (!last) {
                uint32_t off = (uint32_t)(((nxt * RBG + ks) * HSP + col) * 4);
#pragma unroll
                for (int r = 0; r < RNK; r++) {
                    asm volatile("st.shared::cluster.f32 [%0], %1;"
                                 :: "r"(rbase[r] + off), "f"(hvout) : "memory");
                }
            }
            hout[(size_t)(t * 32 + bglob) * 400 + dir * 200 + col] = hvout;
        }
        if (!last) {
            int tn = fwd ? (s + 1) : (LQ - 2 - s);
#pragma unroll
            for (int g = 0; g < 4; g++)
                xv[g] = owner ? xgd[(size_t)(tn * 32 + bglob) * XGP + g * 200 + col]
                              : 0.0f;
        }
    }

    // exit safety: no CTA leaves while peers could still touch its SMEM
    asm volatile("barrier.cluster.arrive.aligned;" ::: "memory");
    asm volatile("barrier.cluster.wait.aligned;"   ::: "memory");
}

// =====================================================================
// Kernel 4: span features (contiguous slabs + evict-first stores)
// =====================================================================
__global__ void __launch_bounds__(256) span_kernel(float* __restrict__ out)
{
    int a     = blockIdx.x;             // 0..125
    int batch = blockIdx.y;             // 0..31
    int N     = 126 - a;                // pairs in this block
    int start = (a * (253 - a)) >> 1;   // first p for this a

    const float* h1 = g_h1;
    __shared__ float4 base4[100];       // 400 floats

    for (int q = threadIdx.x; q < 100; q += 256) {
        int c   = q * 4;
        int row = (q < 50) ? (a * 32 + batch) : ((a + 1) * 32 + batch);
        base4[q] = *(const float4*)(h1 + (size_t)row * 400 + c);
    }
    __syncthreads();

    float* outb = out + (size_t)batch * SPAN_BSTRIDE + (size_t)start * 400;
    int total = N * 100;                // float4 units
    for (int i = threadIdx.x; i < total; i += 256) {
        int j = i / 100, q = i - j * 100;
        int c = q * 4;
        int bpos = a + 1 + j;
        int row  = (q < 50) ? (bpos * 32 + batch) : ((bpos + 1) * 32 + batch);
        float4 cur = *(const float4*)(h1 + (size_t)row * 400 + c);
        float4 bs  = base4[q];
        float4 r;
        if (q < 50) {
            r.x = cur.x - bs.x; r.y = cur.y - bs.y;
            r.z = cur.z - bs.z; r.w = cur.w - bs.w;
        } else {
            r.x = bs.x - cur.x; r.y = bs.y - cur.y;
            r.z = bs.z - cur.z; r.w = bs.w - cur.w;
        }
        __stcs((float4*)(outb + (size_t)j * 400 + c), r);
    }
}

// =====================================================================
// Kernel 5: sentence lengths - 2
// =====================================================================
__global__ void lens_kernel(const int* __restrict__ word, float* __restrict__ out)
{
    int b = threadIdx.x;
    if (b < BQ) {
        int cnt = 0;
        for (int l = 0; l < LQ; l++) cnt += (word[b * LQ + l] != 0);
        out[SPAN_TOTAL + b] = (float)(cnt - 2);
    }
}

// =====================================================================
// launcher  (lens second: keeps ncu's fixed slot on lstm_rec<0>)
// =====================================================================
extern "C" void kernel_launch(void* const* d_in, const int* in_sizes, int n_in,
                              void* d_out, int out_size)
{
    const int*   lang  = (const int*)d_in[0];
    const int*   word  = (const int*)d_in[1];
    const int*   pos   = (const int*)d_in[2];
    const int*   dep   = (const int*)d_in[3];
    const int*   ent   = (const int*)d_in[4];
    const int*   iob   = (const int*)d_in[5];
    const float* El    = (const float*)d_in[6];
    const float* Ew    = (const float*)d_in[7];
    const float* Ep    = (const float*)d_in[8];
    const float* Ed    = (const float*)d_in[9];
    const float* Ee    = (const float*)d_in[10];
    const float* Ei    = (const float*)d_in[11];
    const float* Wih0  = (const float*)d_in[12];
    const float* Whh0  = (const float*)d_in[13];
    const float* bih0  = (const float*)d_in[14];
    const float* bhh0  = (const float*)d_in[15];
    const float* Wih1  = (const float*)d_in[16];
    const float* Whh1  = (const float*)d_in[17];
    const float* bih1  = (const float*)d_in[18];
    const float* bhh1  = (const float*)d_in[19];
    float* out = (float*)d_out;

    emb_kernel<<<MROWS, 256>>>(lang, word, pos, dep, ent, iob, El, Ew, Ep, Ed, Ee, Ei);
    if (out_size >= SPAN_TOTAL + BQ) {
        lens_kernel<<<1, 32>>>(word, out);
    }
    xg_gemm<0><<<dim3(32, 13, 2), 256>>>(Wih0, bih0, bhh0);
    lstm_rec<0><<<128, 256>>>(Whh0);
    xg_gemm<1><<<dim3(32, 13, 2), 256>>>(Wih1, bih1, bhh1);
    lstm_rec<1><<<128, 256>>>(Whh1);
    span_kernel<<<dim3(126, 32), 256>>>(out);
}

// round 17
// speedup vs baseline: 1.0169x; 1.0169x over previous
#include <cuda_runtime.h>
#include <cstdint>
#include <math.h>

// ---------------- problem constants ----------------
#define BQ     32
#define LQ     128
#define HQ     200
#define MROWS  4096          // L*B rows, row m = t*32 + b
#define IND    550
#define KP0    560           // padded K for layer0 A
#define K1     400
#define NG     800           // 4*H gates
#define XGP    832           // padded gate stride (13 * 64)
#define NPAIR  8001
#define SPAN_BSTRIDE (NPAIR*400)          // 3,200,400
#define SPAN_TOTAL   (BQ*NPAIR*400)       // 102,412,800

// recurrence sharding (v9 geometry)
#define RNK    8             // CTAs per cluster (owns 25 h-cols each)
#define RBG    4             // batches per cluster
#define KSL    28            // k elements per k-slice (8*28 = 224 >= 200)
#define HSP    228           // padded hs row stride (floats)
#define NBUF   4             // quad-buffered h exchange
#define SENTINEL 0x7F7FFFFFu // FLT_MAX bits; h = sig*tanh in (-1,1), never this

// ---------------- device scratch (no runtime allocation) ----------------
__device__ float g_x0[MROWS * KP0];          // embedded input, zero-padded K
__device__ float g_xg[2 * MROWS * XGP];      // gate pre-activations (reused both layers)
__device__ float g_h0[MROWS * 400];          // layer0 output  [t*32+b][dir*200+c]
__device__ float g_h1[MROWS * 400];          // layer1 output

// ---------------- helpers ----------------
__device__ __forceinline__ float sigf(float x) {
    return __fdividef(1.0f, 1.0f + __expf(-x));
}
__device__ __forceinline__ float tanh_fast(float x) {
    return 2.0f * __fdividef(1.0f, 1.0f + __expf(-2.0f * x)) - 1.0f;
}

__device__ __forceinline__ uint32_t f2tf32(float x) {
    uint32_t r;
    asm("cvt.rna.tf32.f32 %0, %1;" : "=r"(r) : "f"(x));
    return r;
}

__device__ __forceinline__ unsigned long long packf2(float x, float y) {
    unsigned long long r;
    asm("mov.b64 %0, {%1, %2};" : "=l"(r) : "f"(x), "f"(y));
    return r;
}
__device__ __forceinline__ void unpackf2(unsigned long long v, float& lo, float& hi) {
    asm("mov.b64 {%0, %1}, %2;" : "=f"(lo), "=f"(hi) : "l"(v));
}
__device__ __forceinline__ unsigned long long fma2(unsigned long long a,
                                                   unsigned long long b,
                                                   unsigned long long c) {
    unsigned long long d;
    asm("fma.rn.f32x2 %0, %1, %2, %3;" : "=l"(d) : "l"(a), "l"(b), "l"(c));
    return d;
}
__device__ __forceinline__ uint32_t smem_u32(const void* p) {
    uint32_t a;
    asm("{ .reg .u64 t; cvta.to.shared.u64 t, %1; cvt.u32.u64 %0, t; }"
        : "=r"(a) : "l"(p));
    return a;
}
__device__ __forceinline__ uint32_t mapa_u32(uint32_t addr, uint32_t rank) {
    uint32_t r;
    asm("mapa.shared::cluster.u32 %0, %1, %2;" : "=r"(r) : "r"(addr), "r"(rank));
    return r;
}

// =====================================================================
// Kernel 1: embedding gather
// =====================================================================
__global__ void __launch_bounds__(256) emb_kernel(
    const int* __restrict__ lang, const int* __restrict__ word,
    const int* __restrict__ pos,  const int* __restrict__ dep,
    const int* __restrict__ ent,  const int* __restrict__ iob,
    const float* __restrict__ El, const float* __restrict__ Ew,
    const float* __restrict__ Ep, const float* __restrict__ Ed,
    const float* __restrict__ Ee, const float* __restrict__ Ei)
{
    int m = blockIdx.x;                 // t*32 + b
    int t = m >> 5, b = m & 31;
    int tid = threadIdx.x;

    int li = lang[b * LQ + t];
    int wi = word[b * LQ + t];
    int pi = pos[b * LQ + t];
    int di = dep[b * LQ + t];
    int ei = ent[b * LQ + t];
    int ii = iob[b * LQ + t];

    float* dst = g_x0 + (size_t)m * KP0;
    for (int c = tid; c < KP0; c += 256) {
        float v;
        if      (c < 50)  v = El[li * 50  + c];
        else if (c < 350) v = Ew[wi * 300 + (c - 50)];
        else if (c < 400) v = Ep[pi * 50  + (c - 350)];
        else if (c < 450) v = Ed[di * 50  + (c - 400)];
        else if (c < 500) v = Ee[ei * 50  + (c - 450)];
        else if (c < 550) v = Ei[ii * 50  + (c - 500)];
        else              v = 0.0f;     // K padding for the tf32 GEMM
        dst[c] = v;
    }
}

// =====================================================================
// Kernel 2: xg GEMM  (tf32 mma.sync — reverted to R15-exact version;
// the vectorized fill variant was neutral, so keep the proven one)
// =====================================================================
template<int LAYER>
__global__ void __launch_bounds__(256) xg_gemm(
    const float* __restrict__ W, const float* __restrict__ bi,
    const float* __restrict__ bh)
{
    constexpr int K   = (LAYER == 0) ? IND : K1;
    constexpr int KPA = (LAYER == 0) ? KP0 : K1;
    const float* A = (LAYER == 0) ? g_x0 : g_h0;

    __shared__ uint32_t As[128 * 20];
    __shared__ uint32_t Bs[64 * 20];

    int mt0 = blockIdx.x * 128;
    int nt0 = blockIdx.y * 64;
    int dir = blockIdx.z;
    const float* Wd  = W  + (size_t)dir * NG * K;
    const float* bid = bi + dir * NG;
    const float* bhd = bh + dir * NG;
    float* Cd = g_xg + (size_t)dir * MROWS * XGP;

    int tid  = threadIdx.x;
    int w    = tid >> 5, lane = tid & 31;
    int wm   = w & 3,  wn = w >> 2;
    int gr   = lane >> 2, lc = lane & 3;

    float acc[2][4][4];
#pragma unroll
    for (int a = 0; a < 2; a++)
#pragma unroll
        for (int b2 = 0; b2 < 4; b2++)
#pragma unroll
            for (int c = 0; c < 4; c++) acc[a][b2][c] = 0.0f;

    const int KIT = KPA / 16;
    for (int kt = 0; kt < KIT; kt++) {
        int kbase = kt * 16;
#pragma unroll
        for (int r = 0; r < 2; r++) {
            int q   = tid + r * 256;
            int row = q >> 2, c4 = (q & 3) * 4;
            float4 v = *(const float4*)(A + (size_t)(mt0 + row) * KPA + kbase + c4);
            uint32_t* d = As + row * 20 + c4;
            d[0] = f2tf32(v.x); d[1] = f2tf32(v.y);
            d[2] = f2tf32(v.z); d[3] = f2tf32(v.w);
        }
#pragma unroll
        for (int r = 0; r < 4; r++) {
            int e = tid + r * 256;
            int n = e >> 4, k = e & 15;
            int ng = nt0 + n, gk = kbase + k;
            float v = (ng < NG && gk < K) ? Wd[(size_t)ng * K + gk] : 0.0f;
            Bs[n * 20 + k] = f2tf32(v);
        }
        __syncthreads();

#pragma unroll
        for (int kk = 0; kk < 16; kk += 8) {
            uint32_t af[2][4], bf[4][2];
#pragma unroll
            for (int mt = 0; mt < 2; mt++) {
                int rb = wm * 32 + mt * 16 + gr;
                af[mt][0] = As[rb * 20 + kk + lc];
                af[mt][1] = As[(rb + 8) * 20 + kk + lc];
                af[mt][2] = As[rb * 20 + kk + lc + 4];
                af[mt][3] = As[(rb + 8) * 20 + kk + lc + 4];
            }
#pragma unroll
            for (int nt = 0; nt < 4; nt++) {
                int nb = wn * 32 + nt * 8 + gr;
                bf[nt][0] = Bs[nb * 20 + kk + lc];
                bf[nt][1] = Bs[nb * 20 + kk + lc + 4];
            }
#pragma unroll
            for (int mt = 0; mt < 2; mt++)
#pragma unroll
                for (int nt = 0; nt < 4; nt++) {
                    asm volatile(
                        "mma.sync.aligned.m16n8k8.row.col.f32.tf32.tf32.f32 "
                        "{%0,%1,%2,%3}, {%4,%5,%6,%7}, {%8,%9}, {%0,%1,%2,%3};"
                        : "+f"(acc[mt][nt][0]), "+f"(acc[mt][nt][1]),
                          "+f"(acc[mt][nt][2]), "+f"(acc[mt][nt][3])
                        : "r"(af[mt][0]), "r"(af[mt][1]), "r"(af[mt][2]), "r"(af[mt][3]),
                          "r"(bf[nt][0]), "r"(bf[nt][1]));
                }
        }
        __syncthreads();
    }

#pragma unroll
    for (int mt = 0; mt < 2; mt++) {
        int row0 = mt0 + wm * 32 + mt * 16 + gr;
#pragma unroll
        for (int nt = 0; nt < 4; nt++) {
            int col = nt0 + wn * 32 + nt * 8 + 2 * lc;
            if (col < NG) {
                float bs0 = bid[col] + bhd[col];
                float bs1 = bid[col + 1] + bhd[col + 1];
                Cd[(size_t)row0 * XGP + col]           = acc[mt][nt][0] + bs0;
                Cd[(size_t)row0 * XGP + col + 1]       = acc[mt][nt][1] + bs1;
                Cd[(size_t)(row0 + 8) * XGP + col]     = acc[mt][nt][2] + bs0;
                Cd[(size_t)(row0 + 8) * XGP + col + 1] = acc[mt][nt][3] + bs1;
            }
        }
    }
}

// =====================================================================
// Kernel 3: cluster BiLSTM recurrence (v10 — v9 + backoff + split publish).
// vs v9 (347us/layer):
//   * spin loop backs off with __nanosleep(20) after a failed check —
//     256 polling threads were contending for the same smem port the
//     800 incoming DSMEM stores need (producer-pays crossbar).
//   * publish fan-out split with the idle partner lane (ks>=4, same
//     warp, shfl_xor 4): owner stores ranks 0-3, partner ranks 4-7 —
//     halves the serialized remote-store chain on the critical path.
// Protocol, buffering, ordering arguments unchanged from v9.
// =====================================================================
template<int LAYER>
__global__ void __launch_bounds__(256, 1) __cluster_dims__(RNK, 1, 1)
lstm_rec(const float* __restrict__ Whh)
{
    float* hout = (LAYER == 0) ? g_h0 : g_h1;

    __shared__ float hs[NBUF][RBG][HSP];        // quad-buffered h_prev

    int blk  = blockIdx.x;
    int rank = blk & 7;
    int bg   = (blk >> 3) & 7;          // batch group (4 batches)
    int dir  = blk >> 6;
    const bool fwd = (dir == 0);

    int tid = threadIdx.x;
    int j   = tid >> 3;                 // 0..31 (valid 0..24)
    int ks  = tid & 7;                  // k-slice
    bool jv = (j < 25);
    int col = rank * 25 + j;            // global h column (when jv)
    bool owner   = jv && (ks < RBG);    // computes batch ks
    bool partner = jv && (ks >= RBG);   // publishes for batch ks-4
    int bglob  = bg * RBG + ks;         // owner's global batch

    const float* xgd = g_xg + (size_t)dir * MROWS * XGP;
    const float* Wd  = Whh + (size_t)dir * NG * HQ;

    // ---- Whh slice into registers ----
    unsigned long long w2[4][KSL / 2];
#pragma unroll
    for (int g = 0; g < 4; g++)
#pragma unroll
        for (int kk = 0; kk < KSL / 2; kk++) {
            int k = ks * KSL + kk * 2;
            float2 v = make_float2(0.0f, 0.0f);
            if (jv && k < HQ)
                v = *(const float2*)(Wd + (size_t)(g * 200 + col) * HQ + k);
            w2[g][kk] = packf2(v.x, v.y);
        }

    // ---- spin/prime word assignment: words w = b*200+c, 800 total ----
    int nw = (tid < 800 - 3 * 256) ? 4 : 3;     // threads 0..31 get 4 words
    uint32_t woff[4];
#pragma unroll
    for (int i = 0; i < 4; i++) {
        int w = tid + i * 256;
        if (w < 800) {
            int b = w / 200, c = w - b * 200;
            woff[i] = (uint32_t)((b * HSP + c) * 4);
        } else woff[i] = 0;
    }
    uint32_t hbase0 = smem_u32(&hs[0][0][0]);
    const uint32_t BUFB = (uint32_t)(RBG * HSP * 4);    // bytes per buffer

    // ---- init: buf0 = zeros (h(-1)); bufs 1..3 data cols sentinel ----
    for (int i = tid; i < NBUF * RBG * HSP; i += 256) {
        int buf = i / (RBG * HSP);
        int r   = i - buf * (RBG * HSP);
        int c   = r % HSP;
        ((float*)hs)[i] = (buf != 0 && c < 200) ? __uint_as_float(SENTINEL) : 0.0f;
    }
    float cst = 0.0f;
    __syncthreads();
    asm volatile("barrier.cluster.arrive.aligned;" ::: "memory");
    asm volatile("barrier.cluster.wait.aligned;"   ::: "memory");

    // DSMEM publish addresses
    uint32_t rbase[RNK];
#pragma unroll
    for (int r = 0; r < RNK; r++) rbase[r] = mapa_u32(hbase0, (uint32_t)r);

    // prefetch xg for step 0
    int t0 = fwd ? 0 : (LQ - 1);
    float xv[4];
#pragma unroll
    for (int g = 0; g < 4; g++)
        xv[g] = owner ? xgd[(size_t)(t0 * 32 + bglob) * XGP + g * 200 + col] : 0.0f;

    for (int s = 0; s < LQ; s++) {
        int t   = fwd ? s : (LQ - 1 - s);
        int cur = s & 3, nxt = (s + 1) & 3, prm = (s + 2) & 3;
        bool last = (s + 1 >= LQ);
        uint32_t curb = hbase0 + (uint32_t)cur * BUFB;
        uint32_t prmb = hbase0 + (uint32_t)prm * BUFB;

        // ---- prime buf[(s+2)%4] (off the critical path) ----
        if (s + 2 < LQ) {
            for (int i = 0; i < nw; i++) {
                asm volatile("st.shared.b32 [%0], %1;"
                             :: "r"(prmb + woff[i]), "r"(SENTINEL) : "memory");
            }
        }

        // ---- spin with backoff: wait for step-(s-1) words (skip s=0).
        //      A failed first check drops into nanosleep-paced polling so
        //      the crossbar stays free for the incoming remote stores. ----
        if (s > 0) {
            bool ok = true;
            for (int i = 0; i < nw; i++) {
                uint32_t v;
                asm volatile("ld.volatile.shared.b32 %0, [%1];"
                             : "=r"(v) : "r"(curb + woff[i]));
                ok &= (v != SENTINEL);
            }
            while (!ok) {
                __nanosleep(20);
                ok = true;
                for (int i = 0; i < nw; i++) {
                    uint32_t v;
                    asm volatile("ld.volatile.shared.b32 %0, [%1];"
                                 : "=r"(v) : "r"(curb + woff[i]));
                    ok &= (v != SENTINEL);
                }
            }
        }
        __syncthreads();    // barA: words confirmed + prime ordered before publish

        // ---- partial dots: sb[b][g] = slice-ks dot for batch b, gate g ----
        float sb[RBG][4];
#pragma unroll
        for (int b = 0; b < RBG; b++) {
            const float4* hp = (const float4*)(&hs[cur][b][ks * KSL]);
            unsigned long long a0 = 0ull, a1 = 0ull, a2 = 0ull, a3 = 0ull;
#pragma unroll
            for (int q = 0; q < KSL / 4; q++) {
                float4 hv = hp[q];
                unsigned long long hlo = packf2(hv.x, hv.y);
                unsigned long long hhi = packf2(hv.z, hv.w);
                a0 = fma2(w2[0][2 * q], hlo, a0); a0 = fma2(w2[0][2 * q + 1], hhi, a0);
                a1 = fma2(w2[1][2 * q], hlo, a1); a1 = fma2(w2[1][2 * q + 1], hhi, a1);
                a2 = fma2(w2[2][2 * q], hlo, a2); a2 = fma2(w2[2][2 * q + 1], hhi, a2);
                a3 = fma2(w2[3][2 * q], hlo, a3); a3 = fma2(w2[3][2 * q + 1], hhi, a3);
            }
            float lo, hi;
            unpackf2(a0, lo, hi); sb[b][0] = lo + hi;
            unpackf2(a1, lo, hi); sb[b][1] = lo + hi;
            unpackf2(a2, lo, hi); sb[b][2] = lo + hi;
            unpackf2(a3, lo, hi); sb[b][3] = lo + hi;
        }

        // ---- transpose-reduce over ks (16 shfls) ----
        bool pl = (ks & 1) == 0;
        float k0[4], k2[4];
#pragma unroll
        for (int g = 0; g < 4; g++) {
            float s01 = pl ? sb[1][g] : sb[0][g];
            float s23 = pl ? sb[3][g] : sb[2][g];
            float r01 = __shfl_xor_sync(0xffffffffu, s01, 1);
            float r23 = __shfl_xor_sync(0xffffffffu, s23, 1);
            k0[g] = (pl ? sb[0][g] : sb[1][g]) + r01;
            k2[g] = (pl ? sb[2][g] : sb[3][g]) + r23;
        }
        bool p2 = ((ks >> 1) & 1) == 0;
        float kq[4];
#pragma unroll
        for (int g = 0; g < 4; g++) {
            float sx = p2 ? k2[g] : k0[g];
            float r  = __shfl_xor_sync(0xffffffffu, sx, 2);
            kq[g] = (p2 ? k0[g] : k2[g]) + r;
        }
        bool p4 = (ks >> 2) == 0;
        float sA = p4 ? kq[2] : kq[0];
        float sB = p4 ? kq[3] : kq[1];
        float rA = __shfl_xor_sync(0xffffffffu, sA, 4);
        float rB = __shfl_xor_sync(0xffffffffu, sB, 4);
        float f0 = (p4 ? kq[0] : kq[2]) + rA;
        float f1 = (p4 ? kq[1] : kq[3]) + rB;
        float g2 = __shfl_xor_sync(0xffffffffu, f0, 4);
        float g3 = __shfl_xor_sync(0xffffffffu, f1, 4);

        // ---- activations (owners: 25 cols x 4 batches) ----
        float hvout = 0.0f;
        if (owner) {
            float gi = f0 + xv[0];
            float gf = f1 + xv[1];
            float gg = g2 + xv[2];
            float go = g3 + xv[3];
            float cn = sigf(gf) * cst + sigf(gi) * tanh_fast(gg);
            cst = cn;
            hvout = sigf(go) * tanh_fast(cn);
        }

        // ---- split publish: owner -> ranks 0..3, partner -> ranks 4..7 ----
        float hvp = __shfl_xor_sync(0xffffffffu, hvout, 4);  // partner gets owner's h
        if (!last) {
            if (owner) {
                uint32_t off = (uint32_t)(((nxt * RBG + ks) * HSP + col) * 4);
#pragma unroll
                for (int r = 0; r < RBG; r++) {
                    asm volatile("st.shared::cluster.f32 [%0], %1;"
                                 :: "r"(rbase[r] + off), "f"(hvout) : "memory");
                }
            } else if (partner) {
                uint32_t off = (uint32_t)(((nxt * RBG + (ks - RBG)) * HSP + col) * 4);
#pragma unroll
                for (int r = RBG; r < RNK; r++) {
                    asm volatile("st.shared::cluster.f32 [%0], %1;"
                                 :: "r"(rbase[r] + off), "f"(hvp) : "memory");
                }
            }
        }

        // off the critical path: global h store + next-step xg prefetch
        if (owner)
            hout[(size_t)(t * 32 + bglob) * 400 + dir * 200 + col] = hvout;
        if (!last) {
            int tn = fwd ? (s + 1) : (LQ - 2 - s);
#pragma unroll
            for (int g = 0; g < 4; g++)
                xv[g] = owner ? xgd[(size_t)(tn * 32 + bglob) * XGP + g * 200 + col]
                              : 0.0f;
        }
    }

    // exit safety: no CTA leaves while peers could still touch its SMEM
    asm volatile("barrier.cluster.arrive.aligned;" ::: "memory");
    asm volatile("barrier.cluster.wait.aligned;"   ::: "memory");
}

// =====================================================================
// Kernel 4: span features (contiguous slabs + evict-first stores)
// =====================================================================
__global__ void __launch_bounds__(256) span_kernel(float* __restrict__ out)
{
    int a     = blockIdx.x;             // 0..125
    int batch = blockIdx.y;             // 0..31
    int N     = 126 - a;                // pairs in this block
    int start = (a * (253 - a)) >> 1;   // first p for this a

    const float* h1 = g_h1;
    __shared__ float4 base4[100];       // 400 floats

    for (int q = threadIdx.x; q < 100; q += 256) {
        int c   = q * 4;
        int row = (q < 50) ? (a * 32 + batch) : ((a + 1) * 32 + batch);
        base4[q] = *(const float4*)(h1 + (size_t)row * 400 + c);
    }
    __syncthreads();

    float* outb = out + (size_t)batch * SPAN_BSTRIDE + (size_t)start * 400;
    int total = N * 100;                // float4 units
    for (int i = threadIdx.x; i < total; i += 256) {
        int j = i / 100, q = i - j * 100;
        int c = q * 4;
        int bpos = a + 1 + j;
        int row  = (q < 50) ? (bpos * 32 + batch) : ((bpos + 1) * 32 + batch);
        float4 cur = *(const float4*)(h1 + (size_t)row * 400 + c);
        float4 bs  = base4[q];
        float4 r;
        if (q < 50) {
            r.x = cur.x - bs.x; r.y = cur.y - bs.y;
            r.z = cur.z - bs.z; r.w = cur.w - bs.w;
        } else {
            r.x = bs.x - cur.x; r.y = bs.y - cur.y;
            r.z = bs.z - cur.z; r.w = bs.w - cur.w;
        }
        __stcs((float4*)(outb + (size_t)j * 400 + c), r);
    }
}

// =====================================================================
// Kernel 5: sentence lengths - 2
// =====================================================================
__global__ void lens_kernel(const int* __restrict__ word, float* __restrict__ out)
{
    int b = threadIdx.x;
    if (b < BQ) {
        int cnt = 0;
        for (int l = 0; l < LQ; l++) cnt += (word[b * LQ + l] != 0);
        out[SPAN_TOTAL + b] = (float)(cnt - 2);
    }
}

// =====================================================================
// launcher  (lens second: keeps ncu's fixed slot on lstm_rec<0>)
// =====================================================================
extern "C" void kernel_launch(void* const* d_in, const int* in_sizes, int n_in,
                              void* d_out, int out_size)
{
    const int*   lang  = (const int*)d_in[0];
    const int*   word  = (const int*)d_in[1];
    const int*   pos   = (const int*)d_in[2];
    const int*   dep   = (const int*)d_in[3];
    const int*   ent   = (const int*)d_in[4];
    const int*   iob   = (const int*)d_in[5];
    const float* El    = (const float*)d_in[6];
    const float* Ew    = (const float*)d_in[7];
    const float* Ep    = (const float*)d_in[8];
    const float* Ed    = (const float*)d_in[9];
    const float* Ee    = (const float*)d_in[10];
    const float* Ei    = (const float*)d_in[11];
    const float* Wih0  = (const float*)d_in[12];
    const float* Whh0  = (const float*)d_in[13];
    const float* bih0  = (const float*)d_in[14];
    const float* bhh0  = (const float*)d_in[15];
    const float* Wih1  = (const float*)d_in[16];
    const float* Whh1  = (const float*)d_in[17];
    const float* bih1  = (const float*)d_in[18];
    const float* bhh1  = (const float*)d_in[19];
    float* out = (float*)d_out;

    emb_kernel<<<MROWS, 256>>>(lang, word, pos, dep, ent, iob, El, Ew, Ep, Ed, Ee, Ei);
    if (out_size >= SPAN_TOTAL + BQ) {
        lens_kernel<<<1, 32>>>(word, out);
    }
    xg_gemm<0><<<dim3(32, 13, 2), 256>>>(Wih0, bih0, bhh0);
    lstm_rec<0><<<128, 256>>>(Whh0);
    xg_gemm<1><<<dim3(32, 13, 2), 256>>>(Wih1, bih1, bhh1);
    lstm_rec<1><<<128, 256>>>(Whh1);
    span_kernel<<<dim3(126, 32), 256>>>(out);
}